// round 6
// baseline (speedup 1.0000x reference)
#include <cuda_runtime.h>
#include <math.h>

#define NN 20000
#define EE 640000
#define HID 128

// ---------------- scratch (device globals; no allocation) ----------------
__device__ int   g_is64;
__device__ int   g_flag;           // scan completion counter (reset each call)
__device__ int   g_csrc[EE];       // CSR: src ids grouped by dst
__device__ int   g_icnt[NN];       // in-degree (int)
__device__ int   g_rowptr[NN + 1];
__device__ int   g_cursor[NN];
__device__ int   g_part[64];       // block partial sums for scan
__device__ float g_dinv[NN];       // rsqrt(deg+1)
__device__ float g_x  [NN * HID];
__device__ float g_h1 [NN * HID];
__device__ float g_ns [NN * HID];
__device__ float g_h2 [NN * HID];

// ---------------- small helpers ----------------
__device__ __forceinline__ float gelu_f(float x) {
    return 0.5f * x * (1.0f + erff(x * 0.70710678118654752440f));
}

// packed fp32x2 FMA (Blackwell): acc = a * b + acc, two lanes per instruction
__device__ __forceinline__ void fma2(unsigned long long& acc,
                                     unsigned long long a, unsigned long long b) {
    asm("fma.rn.f32x2 %0, %1, %2, %0;" : "+l"(acc) : "l"(a), "l"(b));
}
__device__ __forceinline__ unsigned long long dup2(float a) {
    unsigned long long r;
    asm("mov.b64 %0, {%1, %1};" : "=l"(r) : "f"(a));
    return r;
}
union F4U2 {
    float4 f;
    struct { unsigned long long lo, hi; } u;
    struct { float x, y, z, w; } s;
};

// ---------------- init: zero icnt + flag, detect edge dtype ----------------
__global__ void init_k(const int* __restrict__ ei_words, int n) {
    int idx = blockIdx.x * blockDim.x + threadIdx.x;
    int stride = gridDim.x * blockDim.x;
    for (int i = idx; i < n; i += stride) g_icnt[i] = 0;
    if (idx == 0) g_flag = 0;
    if (blockIdx.x == 0 && threadIdx.x < 64) {
        // int64 little-endian => high words of first 64 values all zero
        int hi = ei_words[2 * threadIdx.x + 1];
        __shared__ unsigned s[2];
        unsigned b = __ballot_sync(0xFFFFFFFFu, hi != 0);
        if ((threadIdx.x & 31) == 0) s[threadIdx.x >> 5] = b;
        __syncthreads();
        if (threadIdx.x == 0) g_is64 = ((s[0] | s[1]) == 0u) ? 1 : 0;
    }
}

// count in-degree (dst only)
__global__ void count_k(const void* __restrict__ ei, int E) {
    int e = blockIdx.x * blockDim.x + threadIdx.x;
    if (e >= E) return;
    int d;
    if (g_is64) d = (int)((const long long*)ei)[E + e];
    else        d = ((const int*)ei)[E + e];
    atomicAdd(&g_icnt[d], 1);
}

// ---------------- single-launch scan (20 blocks, flag-synchronized) ----------------
__global__ void __launch_bounds__(1024) scan_fused_k(int n) {
    __shared__ int wsum[32];
    __shared__ int s_off;
    int tid = threadIdx.x, lane = tid & 31, wid = tid >> 5;
    int i = blockIdx.x * 1024 + tid;
    int c = (i < n) ? g_icnt[i] : 0;
    int incl = c;
    #pragma unroll
    for (int off = 1; off < 32; off <<= 1) {
        int u = __shfl_up_sync(0xFFFFFFFFu, incl, off);
        if (lane >= off) incl += u;
    }
    if (lane == 31) wsum[wid] = incl;
    __syncthreads();
    if (wid == 0) {
        int t = wsum[lane];
        #pragma unroll
        for (int off = 1; off < 32; off <<= 1) {
            int u = __shfl_up_sync(0xFFFFFFFFu, t, off);
            if (lane >= off) t += u;
        }
        wsum[lane] = t;
    }
    __syncthreads();
    int warp_off = (wid == 0) ? 0 : wsum[wid - 1];
    int local_excl = warp_off + incl - c;
    int block_total = wsum[31];

    // publish partial, wait for all blocks
    if (tid == 0) {
        g_part[blockIdx.x] = block_total;
        __threadfence();
        atomicAdd(&g_flag, 1);
        while (atomicAdd(&g_flag, 0) < (int)gridDim.x) { }
        __threadfence();
        int o = 0;
        for (int b = 0; b < (int)blockIdx.x; b++) o += g_part[b];
        s_off = o;
        if (blockIdx.x == gridDim.x - 1) g_rowptr[n] = o + block_total;
    }
    __syncthreads();
    int run = s_off + local_excl;
    if (i < n) {
        g_rowptr[i] = run;
        g_cursor[i] = run;
        g_dinv[i]   = rsqrtf((float)c + 1.0f);
    }
}

// ---------------- GEMM body (TN=4, CT=32: warp-uniform A loads) ----------------
template<int BN, int ACT>
__device__ __forceinline__ void gemm_body(
    const float* __restrict__ A, const float* __restrict__ W,
    const float* __restrict__ bias, float* __restrict__ C,
    int nrows, int bid)
{
    constexpr int TN  = 4;
    constexpr int CT  = BN / TN;
    constexpr int RT  = 256 / CT;
    constexpr int BM  = 32;
    constexpr int RPT = BM / RT;
    const int tid  = threadIdx.x;
    const int tc   = tid % CT;
    const int tr   = tid / CT;
    const int row0 = bid * BM + tr * RPT;
    const int col0 = tc * TN;
    if (row0 >= nrows) return;

    unsigned long long acc[RPT][2];
    #pragma unroll
    for (int r = 0; r < RPT; r++) { acc[r][0] = 0ull; acc[r][1] = 0ull; }

    for (int k4 = 0; k4 < 128; k4 += 4) {
        F4U2 w0, w1, w2, w3;
        w0.f = *(const float4*)&W[(k4 + 0) * BN + col0];
        w1.f = *(const float4*)&W[(k4 + 1) * BN + col0];
        w2.f = *(const float4*)&W[(k4 + 2) * BN + col0];
        w3.f = *(const float4*)&W[(k4 + 3) * BN + col0];
        #pragma unroll
        for (int r = 0; r < RPT; r++) {
            F4U2 a;
            a.f = *(const float4*)&A[(size_t)(row0 + r) * 128 + k4];
            unsigned long long ax = dup2(a.s.x), ay = dup2(a.s.y),
                               az = dup2(a.s.z), aw = dup2(a.s.w);
            fma2(acc[r][0], ax, w0.u.lo); fma2(acc[r][1], ax, w0.u.hi);
            fma2(acc[r][0], ay, w1.u.lo); fma2(acc[r][1], ay, w1.u.hi);
            fma2(acc[r][0], az, w2.u.lo); fma2(acc[r][1], az, w2.u.hi);
            fma2(acc[r][0], aw, w3.u.lo); fma2(acc[r][1], aw, w3.u.hi);
        }
    }

    #pragma unroll
    for (int r = 0; r < RPT; r++) {
        F4U2 o;
        o.u.lo = acc[r][0]; o.u.hi = acc[r][1];
        float v[4] = {o.s.x, o.s.y, o.s.z, o.s.w};
        #pragma unroll
        for (int c = 0; c < TN; c++) {
            float t = v[c];
            if (bias) t += bias[col0 + c];
            if (ACT == 1) t = fmaxf(t, 0.0f);
            if (ACT == 2) t = gelu_f(t);
            v[c] = t;
        }
        o.s.x = v[0]; o.s.y = v[1]; o.s.z = v[2]; o.s.w = v[3];
        *(float4*)&C[(size_t)(row0 + r) * BN + col0] = o.f;
    }
}

template<int BN, int ACT>
__global__ void __launch_bounds__(256) gemm_k(
    const float* __restrict__ A, const float* __restrict__ W,
    const float* __restrict__ bias, float* __restrict__ C, int nrows)
{
    gemm_body<BN, ACT>(A, W, bias, C, nrows, blockIdx.x);
}

// fused: blocks [0, gb) do GEMM1 (feat@W_gcn), blocks [gb, ..) do CSR fill
__global__ void __launch_bounds__(256) gemm1_fill_k(
    const float* __restrict__ A, const float* __restrict__ W,
    float* __restrict__ C, int nrows, int gb,
    const void* __restrict__ ei, int E)
{
    if ((int)blockIdx.x < gb) {
        gemm_body<128, 0>(A, W, nullptr, C, nrows, blockIdx.x);
    } else {
        int e = (blockIdx.x - gb) * 256 + threadIdx.x;
        if (e >= E) return;
        int s, d;
        if (g_is64) {
            const long long* p = (const long long*)ei;
            s = (int)p[e]; d = (int)p[E + e];
        } else {
            const int* p = (const int*)ei;
            s = p[e]; d = p[E + e];
        }
        int slot = atomicAdd(&g_cursor[d], 1);
        g_csrc[slot] = s;
    }
}

// ---------------- GCN gather (float4/lane): h1 = relu(sum + selfloop + b)
__global__ void gcn_gather_k(const float* __restrict__ bias, int n) {
    int node = blockIdx.x * (blockDim.x >> 5) + (threadIdx.x >> 5);
    if (node >= n) return;
    int lane = threadIdx.x & 31;
    int beg = g_rowptr[node], end = g_rowptr[node + 1];
    float dd = g_dinv[node];
    const float4* xd = (const float4*)(g_x + (size_t)node * HID);
    float4 sv = xd[lane];
    float sl = dd * dd;
    float4 acc;
    acc.x = sv.x * sl; acc.y = sv.y * sl; acc.z = sv.z * sl; acc.w = sv.w * sl;

    int e = beg;
    for (; e + 1 < end; e += 2) {
        int s0 = g_csrc[e], s1 = g_csrc[e + 1];
        float c0 = g_dinv[s0] * dd, c1 = g_dinv[s1] * dd;
        float4 v0 = ((const float4*)(g_x + (size_t)s0 * HID))[lane];
        float4 v1 = ((const float4*)(g_x + (size_t)s1 * HID))[lane];
        acc.x = fmaf(v0.x, c0, acc.x); acc.y = fmaf(v0.y, c0, acc.y);
        acc.z = fmaf(v0.z, c0, acc.z); acc.w = fmaf(v0.w, c0, acc.w);
        acc.x = fmaf(v1.x, c1, acc.x); acc.y = fmaf(v1.y, c1, acc.y);
        acc.z = fmaf(v1.z, c1, acc.z); acc.w = fmaf(v1.w, c1, acc.w);
    }
    if (e < end) {
        int s0 = g_csrc[e];
        float c0 = g_dinv[s0] * dd;
        float4 v0 = ((const float4*)(g_x + (size_t)s0 * HID))[lane];
        acc.x = fmaf(v0.x, c0, acc.x); acc.y = fmaf(v0.y, c0, acc.y);
        acc.z = fmaf(v0.z, c0, acc.z); acc.w = fmaf(v0.w, c0, acc.w);
    }
    float4 b4 = ((const float4*)bias)[lane];
    float4 o;
    o.x = fmaxf(acc.x + b4.x, 0.0f);
    o.y = fmaxf(acc.y + b4.y, 0.0f);
    o.z = fmaxf(acc.z + b4.z, 0.0f);
    o.w = fmaxf(acc.w + b4.w, 0.0f);
    ((float4*)(g_h1 + (size_t)node * HID))[lane] = o;
}

// ---------------- SAGE gather (float4/lane): ns = mean_neigh h1[s]
__global__ void sage_gather_k(int n) {
    int node = blockIdx.x * (blockDim.x >> 5) + (threadIdx.x >> 5);
    if (node >= n) return;
    int lane = threadIdx.x & 31;
    int beg = g_rowptr[node], end = g_rowptr[node + 1];
    float4 acc = make_float4(0.f, 0.f, 0.f, 0.f);
    int e = beg;
    for (; e + 1 < end; e += 2) {
        int s0 = g_csrc[e], s1 = g_csrc[e + 1];
        float4 v0 = ((const float4*)(g_h1 + (size_t)s0 * HID))[lane];
        float4 v1 = ((const float4*)(g_h1 + (size_t)s1 * HID))[lane];
        acc.x += v0.x + v1.x; acc.y += v0.y + v1.y;
        acc.z += v0.z + v1.z; acc.w += v0.w + v1.w;
    }
    if (e < end) {
        int s0 = g_csrc[e];
        float4 v0 = ((const float4*)(g_h1 + (size_t)s0 * HID))[lane];
        acc.x += v0.x; acc.y += v0.y; acc.z += v0.z; acc.w += v0.w;
    }
    int deg = end - beg;
    float inv = 1.0f / (float)max(deg, 1);
    acc.x *= inv; acc.y *= inv; acc.z *= inv; acc.w *= inv;
    ((float4*)(g_ns + (size_t)node * HID))[lane] = acc;
}

// fused SAGE GEMM + value head: h2 = relu(ns@Wl + h1@Wr + bl); values = h2@Wv + bv
__global__ void __launch_bounds__(256) gemm2_k(
    const float* __restrict__ A1, const float* __restrict__ W1,
    const float* __restrict__ A2, const float* __restrict__ W2,
    const float* __restrict__ bias,
    float* __restrict__ C, int nrows,
    const float* __restrict__ Wv, const float* __restrict__ bv,
    float* __restrict__ values_out)
{
    constexpr int BN = 128, TN = 4, CT = 32, RPT = 4, BM = 32;
    const int tid  = threadIdx.x;
    const int tc   = tid % CT;       // == lane
    const int tr   = tid / CT;       // == warp
    const int row0 = blockIdx.x * BM + tr * RPT;
    const int col0 = tc * TN;
    if (row0 >= nrows) return;

    unsigned long long acc[RPT][2];
    #pragma unroll
    for (int r = 0; r < RPT; r++) { acc[r][0] = 0ull; acc[r][1] = 0ull; }

    #pragma unroll 1
    for (int pass = 0; pass < 2; pass++) {
        const float* A = pass ? A2 : A1;
        const float* W = pass ? W2 : W1;
        for (int k4 = 0; k4 < 128; k4 += 4) {
            F4U2 w0, w1, w2, w3;
            w0.f = *(const float4*)&W[(k4 + 0) * BN + col0];
            w1.f = *(const float4*)&W[(k4 + 1) * BN + col0];
            w2.f = *(const float4*)&W[(k4 + 2) * BN + col0];
            w3.f = *(const float4*)&W[(k4 + 3) * BN + col0];
            #pragma unroll
            for (int r = 0; r < RPT; r++) {
                F4U2 a;
                a.f = *(const float4*)&A[(size_t)(row0 + r) * 128 + k4];
                unsigned long long ax = dup2(a.s.x), ay = dup2(a.s.y),
                                   az = dup2(a.s.z), aw = dup2(a.s.w);
                fma2(acc[r][0], ax, w0.u.lo); fma2(acc[r][1], ax, w0.u.hi);
                fma2(acc[r][0], ay, w1.u.lo); fma2(acc[r][1], ay, w1.u.hi);
                fma2(acc[r][0], az, w2.u.lo); fma2(acc[r][1], az, w2.u.hi);
                fma2(acc[r][0], aw, w3.u.lo); fma2(acc[r][1], aw, w3.u.hi);
            }
        }
    }

    float4 wv = *(const float4*)&Wv[col0];
    float bv0 = bv[0];
    #pragma unroll
    for (int r = 0; r < RPT; r++) {
        F4U2 o;
        o.u.lo = acc[r][0]; o.u.hi = acc[r][1];
        o.s.x = fmaxf(o.s.x + bias[col0 + 0], 0.0f);
        o.s.y = fmaxf(o.s.y + bias[col0 + 1], 0.0f);
        o.s.z = fmaxf(o.s.z + bias[col0 + 2], 0.0f);
        o.s.w = fmaxf(o.s.w + bias[col0 + 3], 0.0f);
        *(float4*)&C[(size_t)(row0 + r) * BN + col0] = o.f;
        // value-head partial: dot of this row with Wv across the warp
        float p = fmaf(o.s.x, wv.x, fmaf(o.s.y, wv.y,
                  fmaf(o.s.z, wv.z, o.s.w * wv.w)));
        #pragma unroll
        for (int off = 16; off > 0; off >>= 1)
            p += __shfl_xor_sync(0xFFFFFFFFu, p, off);
        if (tc == 0) values_out[row0 + r] = p + bv0;
    }
}

// ---------------- launch ----------------
extern "C" void kernel_launch(void* const* d_in, const int* in_sizes, int n_in,
                              void* d_out, int out_size)
{
    const float* feat     = (const float*)d_in[0];
    const void*  ei       = d_in[1];
    const float* W_gcn    = (const float*)d_in[2];
    const float* b_gcn    = (const float*)d_in[3];
    const float* W_sage_l = (const float*)d_in[4];
    const float* b_sage_l = (const float*)d_in[5];
    const float* W_sage_r = (const float*)d_in[6];
    const float* W1       = (const float*)d_in[7];
    const float* b1       = (const float*)d_in[8];
    const float* W2       = (const float*)d_in[9];
    const float* b2       = (const float*)d_in[10];
    const float* W3       = (const float*)d_in[11];
    const float* b3       = (const float*)d_in[12];
    const float* Wv       = (const float*)d_in[13];
    const float* bv       = (const float*)d_in[14];

    const int N = in_sizes[0] / HID;   // 20000
    const int E = in_sizes[1] / 2;     // 640000

    float* means_out  = (float*)d_out;            // [N, 64]
    float* values_out = (float*)d_out + (size_t)N * 64;

    float *p_x, *p_h1, *p_ns, *p_h2;
    cudaGetSymbolAddress((void**)&p_x,  g_x);
    cudaGetSymbolAddress((void**)&p_h1, g_h1);
    cudaGetSymbolAddress((void**)&p_ns, g_ns);
    cudaGetSymbolAddress((void**)&p_h2, g_h2);

    const int TB = 256;
    const int e_blocks   = (E + TB - 1) / TB;
    const int nw_blocks  = (N * 32 + TB - 1) / TB;   // warp per node
    const int scan_blocks = (N + 1023) / 1024;       // 20
    const int gemm_blocks = (N + 31) / 32;           // 625

    // 1) init (zero icnt+flag, detect dtype)
    init_k<<<80, TB>>>((const int*)ei, N);
    // 2) in-degree count
    count_k<<<e_blocks, TB>>>(ei, E);
    // 3) single-launch synchronized scan -> rowptr/cursor/dinv
    scan_fused_k<<<scan_blocks, 1024>>>(N);
    // 4) GEMM1 (feat@W_gcn) co-running with CSR fill
    gemm1_fill_k<<<gemm_blocks + e_blocks, TB>>>(feat, W_gcn, p_x, N,
                                                 gemm_blocks, ei, E);
    // 5) GCN gather (+selfloop+bias+relu)
    gcn_gather_k<<<nw_blocks, TB>>>(b_gcn, N);
    // 6) SAGE gather (mean)
    sage_gather_k<<<nw_blocks, TB>>>(N);
    // 7) fused SAGE GEMM + value head
    gemm2_k<<<gemm_blocks, TB>>>(p_ns, W_sage_l, p_h1, W_sage_r, b_sage_l,
                                 p_h2, N, Wv, bv, values_out);
    // 8-10) policy MLP
    gemm_k<128, 2><<<gemm_blocks, TB>>>(p_h2, W1, b1, p_x, N);
    gemm_k<128, 2><<<gemm_blocks, TB>>>(p_x, W2, b2, p_ns, N);
    gemm_k<64, 0><<<gemm_blocks, TB>>>(p_ns, W3, b3, means_out, N);
}